// round 2
// baseline (speedup 1.0000x reference)
#include <cuda_runtime.h>
#include <cuda_bf16.h>
#include <stdint.h>

// ---------------- problem constants ----------------
#define N_NODES 16384
#define NE      524288
#define IN_F    128
#define OUT_F   64

// ---------------- device scratch (no mallocs allowed) ----------------
__device__ float         g_hw [N_NODES * OUT_F];   // 4 MB
__device__ float         g_agg[N_NODES * OUT_F];   // 4 MB
__device__ __nv_bfloat16 g_xhi[N_NODES * OUT_F];   // 2 MB
__device__ __nv_bfloat16 g_xlo[N_NODES * OUT_F];   // 2 MB
__device__ int           g_is64;

// ---------------- kernel 0: int32/int64 index-width detection ----------------
__global__ void detect_kernel(const unsigned int* __restrict__ w) {
    __shared__ int cnt;
    if (threadIdx.x == 0) cnt = 0;
    __syncthreads();
    int z = 0;
    for (int i = threadIdx.x; i < 1024; i += 256)
        z += (w[2 * i + 1] == 0u) ? 1 : 0;
    atomicAdd(&cnt, z);
    __syncthreads();
    if (threadIdx.x == 0) g_is64 = (cnt > 512) ? 1 : 0;
}

// ---------------- kernel 1: hw = h @ W, and zero agg ----------------
__global__ __launch_bounds__(256) void k1_proj(const float* __restrict__ h,
                                               const float* __restrict__ W) {
    __shared__ float sW[IN_F * OUT_F];  // 32 KB
    __shared__ float sH[8][IN_F];       // 4 KB
    int tid = threadIdx.x, wid = tid >> 5, lid = tid & 31;
    for (int i = tid; i < IN_F * OUT_F; i += 256) sW[i] = W[i];
    int r = blockIdx.x * 8 + wid;
    #pragma unroll
    for (int t = 0; t < 4; t++) sH[wid][lid + 32 * t] = h[(size_t)r * IN_F + lid + 32 * t];
    __syncthreads();
    float a0 = 0.f, a1 = 0.f;
    #pragma unroll
    for (int k = 0; k < IN_F; k++) {
        float hv = sH[wid][k];
        a0 += hv * sW[k * OUT_F + lid];
        a1 += hv * sW[k * OUT_F + lid + 32];
    }
    g_hw [r * OUT_F + lid]      = a0;
    g_hw [r * OUT_F + lid + 32] = a1;
    g_agg[r * OUT_F + lid]      = 0.f;
    g_agg[r * OUT_F + lid + 32] = 0.f;
}

// ---------------- kernel 2: edge scatter-add (one warp per edge) ----------------
__global__ __launch_bounds__(256) void k2_scatter(const unsigned int* __restrict__ srcw,
                                                  const unsigned int* __restrict__ dstw) {
    int gw = (int)((blockIdx.x * 256u + threadIdx.x) >> 5);  // edge id
    int lane = threadIdx.x & 31;
    if (gw >= NE) return;
    int mul = g_is64 ? 2 : 1;
    unsigned s = srcw[(size_t)gw * mul];
    unsigned d = dstw[(size_t)gw * mul];
    float v0 = g_hw[s * OUT_F + lane];
    float v1 = g_hw[s * OUT_F + lane + 32];
    atomicAdd(&g_agg[d * OUT_F + lane],      v0);
    atomicAdd(&g_agg[d * OUT_F + lane + 32], v1);
}

// ---------------- threefry2x32 (JAX-exact, 20 rounds) ----------------
__device__ __forceinline__ void threefry2x32(uint32_t k0, uint32_t k1,
                                             uint32_t x0, uint32_t x1,
                                             uint32_t& o0, uint32_t& o1) {
    uint32_t ks0 = k0, ks1 = k1, ks2 = 0x1BD11BDAu ^ k0 ^ k1;
    x0 += ks0; x1 += ks1;
#define TF_R(rr) { x0 += x1; x1 = (x1 << (rr)) | (x1 >> (32 - (rr))); x1 ^= x0; }
    TF_R(13) TF_R(15) TF_R(26) TF_R(6)  x0 += ks1; x1 += ks2 + 1u;
    TF_R(17) TF_R(29) TF_R(16) TF_R(24) x0 += ks2; x1 += ks0 + 2u;
    TF_R(13) TF_R(15) TF_R(26) TF_R(6)  x0 += ks0; x1 += ks1 + 3u;
    TF_R(17) TF_R(29) TF_R(16) TF_R(24) x0 += ks1; x1 += ks2 + 4u;
    TF_R(13) TF_R(15) TF_R(26) TF_R(6)  x0 += ks2; x1 += ks0 + 5u;
#undef TF_R
    o0 = x0; o1 = x1;
}

// ---------------- kernel 3: relu + dropout mask + bf16 hi/lo split ----------------
// JAX threefry_partitionable=True path: counts = iota(u64); 32-bit draw = out0 ^ out1
// of threefry2x32(key, (count>>32, count&0xffffffff)). key(42) -> (0, 42).
__global__ __launch_bounds__(256) void k3_mask(const float* __restrict__ bias) {
    int i = blockIdx.x * 256 + threadIdx.x;  // i < N*OUT_F = 1048576
    uint32_t o0, o1;
    threefry2x32(0u, 42u, 0u, (uint32_t)i, o0, o1);
    uint32_t bits = o0 ^ o1;
    float u = __uint_as_float((bits >> 9) | 0x3f800000u) - 1.0f;  // uniform [0,1)
    float v = g_agg[i] + bias[i & 63];
    v = fmaxf(v, 0.0f);
    float y = (u < 0.7f) ? (v / 0.7f) : 0.0f;
    __nv_bfloat16 hi = __float2bfloat16(y);
    float lof = y - __bfloat162float(hi);
    g_xhi[i] = hi;
    g_xlo[i] = __float2bfloat16(lof);
}

// ---------------- kernel 4: out = x @ x^T via mma.sync bf16 (hi/lo split) ----------------
// 128x128 tile per CTA, 8 warps in a 4x2 grid, each warp 32x64.
// Operands K-major (64 bf16 = 128 B/row), SW128 XOR swizzle; ldmatrix folds
// the swizzle into (chunk ^ (lane&7)) since row-tile bases are multiples of 16.
// 3 products (hi*hi, hi*lo, lo*hi) accumulated in fp32 registers.
// Epilogue stages through smem (row stride 136 floats) for coalesced float4 stores.
#define SM_AHI  0
#define SM_ALO  16384
#define SM_BHI  32768
#define SM_BLO  49152
#define STAGE_STRIDE 136
#define SM_TOTAL (128 * STAGE_STRIDE * 4)   // 69632 B (operands 65536 B overlap)

__device__ __forceinline__ void ldsm_x4(uint32_t* r, uint32_t addr) {
    asm volatile("ldmatrix.sync.aligned.m8n8.x4.shared.b16 {%0,%1,%2,%3}, [%4];"
                 : "=r"(r[0]), "=r"(r[1]), "=r"(r[2]), "=r"(r[3]) : "r"(addr));
}
__device__ __forceinline__ void mma16816(float* d, const uint32_t* a,
                                         uint32_t b0, uint32_t b1) {
    asm volatile(
        "mma.sync.aligned.m16n8k16.row.col.f32.bf16.bf16.f32 "
        "{%0,%1,%2,%3}, {%4,%5,%6,%7}, {%8,%9}, {%0,%1,%2,%3};"
        : "+f"(d[0]), "+f"(d[1]), "+f"(d[2]), "+f"(d[3])
        : "r"(a[0]), "r"(a[1]), "r"(a[2]), "r"(a[3]), "r"(b0), "r"(b1));
}

__global__ __launch_bounds__(256, 1)
void k4_gemm(float* __restrict__ out) {
    extern __shared__ char smem[];
    uint32_t sb = (uint32_t)__cvta_generic_to_shared(smem);
    int tid = threadIdx.x, wid = tid >> 5, lid = tid & 31;
    int wm = wid & 3, wn = wid >> 2;            // warp tile: rows wm*32, cols wn*64
    int rowA = blockIdx.y << 7;                 // output rows of this CTA
    int rowB = blockIdx.x << 7;                 // output cols of this CTA

    // ---- load 4 operand tiles (each 128 rows x 128 B) with SW128 swizzle ----
    {
        const __nv_bfloat16* bases[4] = {
            g_xhi + (size_t)rowA * OUT_F, g_xlo + (size_t)rowA * OUT_F,
            g_xhi + (size_t)rowB * OUT_F, g_xlo + (size_t)rowB * OUT_F };
        const int offs[4] = { SM_AHI, SM_ALO, SM_BHI, SM_BLO };
        #pragma unroll
        for (int t = 0; t < 4; t++) {
            const uint4* sp = (const uint4*)bases[t];
            #pragma unroll
            for (int j = 0; j < 4; j++) {
                int idx = tid + j * 256;                 // 1024 x 16B chunks
                uint4 v = sp[idx];
                uint32_t bo = (uint32_t)(idx << 4);      // r*128 + c*16
                uint32_t sw = bo ^ ((bo >> 3) & 0x70);
                *(uint4*)(smem + offs[t] + sw) = v;
            }
        }
    }
    __syncthreads();

    // ---- mainloop: 3 products x 4 k-chunks ----
    float acc[2][8][4];
    #pragma unroll
    for (int mt = 0; mt < 2; mt++)
        #pragma unroll
        for (int nt = 0; nt < 8; nt++)
            #pragma unroll
            for (int e = 0; e < 4; e++) acc[mt][nt][e] = 0.f;

    // lane-address terms (swizzle folded: row&7 == lid&7 because tile bases % 16 == 0)
    int lrow = lid & 15;            // row within 16-row ldmatrix tile
    int lchk = lid >> 4;            // 16B-chunk half (k half)
    int lswz = lid & 7;             // swizzle xor term

    const int aoff[3] = { SM_AHI, SM_AHI, SM_ALO };
    const int boff[3] = { SM_BHI, SM_BLO, SM_BHI };

    #pragma unroll
    for (int p = 0; p < 3; p++) {
        uint32_t Abase = sb + aoff[p];
        uint32_t Bbase = sb + boff[p];
        #pragma unroll
        for (int kc = 0; kc < 4; kc++) {
            uint32_t chunk = (uint32_t)(((2 * kc + lchk) ^ lswz) << 4);
            uint32_t a[2][4];
            #pragma unroll
            for (int mt = 0; mt < 2; mt++) {
                int r = wm * 32 + mt * 16 + lrow;
                ldsm_x4(a[mt], Abase + (uint32_t)(r * 128) + chunk);
            }
            uint32_t bq[4][4];
            #pragma unroll
            for (int np = 0; np < 4; np++) {
                int r = wn * 64 + np * 16 + lrow;
                ldsm_x4(bq[np], Bbase + (uint32_t)(r * 128) + chunk);
            }
            #pragma unroll
            for (int mt = 0; mt < 2; mt++)
                #pragma unroll
                for (int nt = 0; nt < 8; nt++) {
                    int np = nt >> 1, sel = nt & 1;
                    mma16816(acc[mt][nt], a[mt], bq[np][sel], bq[np][sel + 2]);
                }
        }
    }
    __syncthreads();   // operands dead; reuse smem as fp32 stage

    // ---- epilogue: fragments -> smem stage -> coalesced global stores ----
    float* stage = (float*)smem;    // [128][STAGE_STRIDE]
    int gid = lid >> 2, tig = lid & 3;
    #pragma unroll
    for (int mt = 0; mt < 2; mt++)
        #pragma unroll
        for (int half = 0; half < 2; half++) {
            int r = wm * 32 + mt * 16 + gid + 8 * half;
            #pragma unroll
            for (int nt = 0; nt < 8; nt++) {
                int c = wn * 64 + nt * 8 + tig * 2;
                *(float2*)&stage[r * STAGE_STRIDE + c] =
                    make_float2(acc[mt][nt][half * 2], acc[mt][nt][half * 2 + 1]);
            }
        }
    __syncthreads();

    {
        size_t obase = (size_t)rowA * 16384 + rowB;
        #pragma unroll
        for (int it = 0; it < 16; it++) {
            int r = it * 8 + wid;
            float4 v = *(float4*)&stage[r * STAGE_STRIDE + lid * 4];
            *(float4*)(out + obase + (size_t)r * 16384 + lid * 4) = v;
        }
    }
}

// ---------------- launch ----------------
extern "C" void kernel_launch(void* const* d_in, const int* in_sizes, int n_in,
                              void* d_out, int out_size) {
    const float*        h    = (const float*)d_in[0];
    const unsigned int* srcw = (const unsigned int*)d_in[1];
    const unsigned int* dstw = (const unsigned int*)d_in[2];
    const float*        W    = (const float*)d_in[3];
    const float*        bias = (const float*)d_in[4];
    float*              out  = (float*)d_out;

    detect_kernel<<<1, 256>>>(srcw);
    k1_proj<<<N_NODES / 8, 256>>>(h, W);
    k2_scatter<<<(NE * 32) / 256, 256>>>(srcw, dstw);
    k3_mask<<<(N_NODES * OUT_F) / 256, 256>>>(bias);

    cudaFuncSetAttribute(k4_gemm, cudaFuncAttributeMaxDynamicSharedMemorySize, SM_TOTAL);
    k4_gemm<<<dim3(128, 128), 256, SM_TOTAL>>>(out);
}

// round 3
// speedup vs baseline: 1.0392x; 1.0392x over previous
#include <cuda_runtime.h>
#include <cuda_bf16.h>
#include <stdint.h>

// ---------------- problem constants ----------------
#define N_NODES 16384
#define NE      524288
#define IN_F    128
#define OUT_F   64

// ---------------- device scratch (no mallocs allowed) ----------------
__device__ float         g_hw [N_NODES * OUT_F];   // 4 MB
__device__ __nv_bfloat16 g_xhi[N_NODES * OUT_F];   // 2 MB
__device__ __nv_bfloat16 g_xlo[N_NODES * OUT_F];   // 2 MB
__device__ int           g_deg[N_NODES];
__device__ int           g_off[N_NODES + 1];
__device__ int           g_cur[N_NODES];
__device__ int           g_srcs[NE];
__device__ int           g_is64;

// ---------------- kernel 0: int32/int64 index-width detection ----------------
__global__ void detect_kernel(const unsigned int* __restrict__ w) {
    __shared__ int cnt;
    if (threadIdx.x == 0) cnt = 0;
    __syncthreads();
    int z = 0;
    for (int i = threadIdx.x; i < 1024; i += 256)
        z += (w[2 * i + 1] == 0u) ? 1 : 0;
    atomicAdd(&cnt, z);
    __syncthreads();
    if (threadIdx.x == 0) g_is64 = (cnt > 512) ? 1 : 0;
}

// ---------------- zero deg/cursor ----------------
__global__ void kz_zero() {
    int i = blockIdx.x * 256 + threadIdx.x;
    g_deg[i] = 0;
    g_cur[i] = 0;
}

// ---------------- kernel 1: hw = h @ W ----------------
__global__ __launch_bounds__(256) void k1_proj(const float* __restrict__ h,
                                               const float* __restrict__ W) {
    __shared__ float sW[IN_F * OUT_F];  // 32 KB
    __shared__ float sH[8][IN_F];       // 4 KB
    int tid = threadIdx.x, wid = tid >> 5, lid = tid & 31;
    for (int i = tid; i < IN_F * OUT_F; i += 256) sW[i] = W[i];
    int r = blockIdx.x * 8 + wid;
    #pragma unroll
    for (int t = 0; t < 4; t++) sH[wid][lid + 32 * t] = h[(size_t)r * IN_F + lid + 32 * t];
    __syncthreads();
    float a0 = 0.f, a1 = 0.f;
    #pragma unroll
    for (int k = 0; k < IN_F; k++) {
        float hv = sH[wid][k];
        a0 += hv * sW[k * OUT_F + lid];
        a1 += hv * sW[k * OUT_F + lid + 32];
    }
    g_hw[r * OUT_F + lid]      = a0;
    g_hw[r * OUT_F + lid + 32] = a1;
}

// ---------------- CSR build: histogram ----------------
__global__ __launch_bounds__(256) void k2a_hist(const unsigned int* __restrict__ dstw) {
    int e = blockIdx.x * 256 + threadIdx.x;
    int mul = g_is64 ? 2 : 1;
    unsigned d = dstw[(size_t)e * mul];
    atomicAdd(&g_deg[d], 1);
}

// ---------------- CSR build: prefix scan (1 block, 1024 threads) ----------------
__global__ __launch_bounds__(1024) void k2b_scan() {
    __shared__ int part[1024];
    int t = threadIdx.x;
    int base = t * 16;
    int loc[16];
    int s = 0;
    #pragma unroll
    for (int k = 0; k < 16; k++) { loc[k] = s; s += g_deg[base + k]; }
    part[t] = s;
    __syncthreads();
    for (int off = 1; off < 1024; off <<= 1) {
        int v = (t >= off) ? part[t - off] : 0;
        __syncthreads();
        part[t] += v;
        __syncthreads();
    }
    int excl = part[t] - s;
    #pragma unroll
    for (int k = 0; k < 16; k++) g_off[base + k] = excl + loc[k];
    if (t == 1023) g_off[N_NODES] = part[1023];
}

// ---------------- CSR build: fill ----------------
__global__ __launch_bounds__(256) void k2c_fill(const unsigned int* __restrict__ srcw,
                                                const unsigned int* __restrict__ dstw) {
    int e = blockIdx.x * 256 + threadIdx.x;
    int mul = g_is64 ? 2 : 1;
    unsigned s = srcw[(size_t)e * mul];
    unsigned d = dstw[(size_t)e * mul];
    int p = atomicAdd(&g_cur[d], 1);
    g_srcs[g_off[d] + p] = (int)s;
}

// ---------------- threefry2x32 (JAX-exact, 20 rounds) ----------------
__device__ __forceinline__ void threefry2x32(uint32_t k0, uint32_t k1,
                                             uint32_t x0, uint32_t x1,
                                             uint32_t& o0, uint32_t& o1) {
    uint32_t ks0 = k0, ks1 = k1, ks2 = 0x1BD11BDAu ^ k0 ^ k1;
    x0 += ks0; x1 += ks1;
#define TF_R(rr) { x0 += x1; x1 = (x1 << (rr)) | (x1 >> (32 - (rr))); x1 ^= x0; }
    TF_R(13) TF_R(15) TF_R(26) TF_R(6)  x0 += ks1; x1 += ks2 + 1u;
    TF_R(17) TF_R(29) TF_R(16) TF_R(24) x0 += ks2; x1 += ks0 + 2u;
    TF_R(13) TF_R(15) TF_R(26) TF_R(6)  x0 += ks0; x1 += ks1 + 3u;
    TF_R(17) TF_R(29) TF_R(16) TF_R(24) x0 += ks1; x1 += ks2 + 4u;
    TF_R(13) TF_R(15) TF_R(26) TF_R(6)  x0 += ks2; x1 += ks0 + 5u;
#undef TF_R
    o0 = x0; o1 = x1;
}

// mask+relu+dropout+split for element index i with aggregated value v
__device__ __forceinline__ void finish_elem(int i, float v) {
    uint32_t o0, o1;
    threefry2x32(0u, 42u, 0u, (uint32_t)i, o0, o1);
    uint32_t bits = o0 ^ o1;
    float u = __uint_as_float((bits >> 9) | 0x3f800000u) - 1.0f;
    v = fmaxf(v, 0.0f);
    float y = (u < 0.7f) ? (v / 0.7f) : 0.0f;
    __nv_bfloat16 hi = __float2bfloat16(y);
    g_xhi[i] = hi;
    g_xlo[i] = __float2bfloat16(y - __bfloat162float(hi));
}

// ---------------- kernel 2d: gather-aggregate + fused epilogue (replaces scatter + k3) ----
__global__ __launch_bounds__(256) void k2d_gather(const float* __restrict__ bias) {
    int wid = threadIdx.x >> 5, lane = threadIdx.x & 31;
    int node = blockIdx.x * 8 + wid;
    int beg = g_off[node], end = g_off[node + 1];
    float a0 = 0.f, a1 = 0.f;
    #pragma unroll 4
    for (int k = beg; k < end; k++) {
        int s = g_srcs[k];
        a0 += g_hw[s * OUT_F + lane];
        a1 += g_hw[s * OUT_F + lane + 32];
    }
    int i0 = node * OUT_F + lane;
    finish_elem(i0,      a0 + bias[lane]);
    finish_elem(i0 + 32, a1 + bias[lane + 32]);
}

// ---------------- kernel 4: out = x @ x^T, symmetric (triangular grid) ----------------
// One CTA per unordered tile pair (i<=j): computes 128x128 tile (i,j), writes it
// and (if i!=j) its transpose at (j,i). 8 warps (4x2), warp tile 32x64.
// hi/lo fragments loaded once per k-chunk and reused by all 3 products.
#define SM_AHI  0
#define SM_ALO  16384
#define SM_BHI  32768
#define SM_BLO  49152
#define STAGE_STRIDE 136
#define SM_TOTAL (128 * STAGE_STRIDE * 4)   // 69632 B

__device__ __forceinline__ void ldsm_x4(uint32_t* r, uint32_t addr) {
    asm volatile("ldmatrix.sync.aligned.m8n8.x4.shared.b16 {%0,%1,%2,%3}, [%4];"
                 : "=r"(r[0]), "=r"(r[1]), "=r"(r[2]), "=r"(r[3]) : "r"(addr));
}
__device__ __forceinline__ void mma16816(float* d, const uint32_t* a,
                                         uint32_t b0, uint32_t b1) {
    asm volatile(
        "mma.sync.aligned.m16n8k16.row.col.f32.bf16.bf16.f32 "
        "{%0,%1,%2,%3}, {%4,%5,%6,%7}, {%8,%9}, {%0,%1,%2,%3};"
        : "+f"(d[0]), "+f"(d[1]), "+f"(d[2]), "+f"(d[3])
        : "r"(a[0]), "r"(a[1]), "r"(a[2]), "r"(a[3]), "r"(b0), "r"(b1));
}

__global__ __launch_bounds__(256, 1)
void k4_gemm(float* __restrict__ out) {
    extern __shared__ char smem[];
    uint32_t sb = (uint32_t)__cvta_generic_to_shared(smem);
    int tid = threadIdx.x, wid = tid >> 5, lid = tid & 31;
    int wm = wid & 3, wn = wid >> 2;

    // triangular decode: bid -> (ti <= tj)
    int bid = blockIdx.x;
    int ti = (int)((257.0 - sqrt(66049.0 - 8.0 * (double)bid)) * 0.5);
    while ((ti + 1) * 128 - ((ti + 1) * ti) / 2 <= bid) ti++;
    while (ti * 128 - (ti * (ti - 1)) / 2 > bid) ti--;
    int tj = ti + (bid - (ti * 128 - (ti * (ti - 1)) / 2));
    int rowA = ti << 7;   // output row block
    int rowB = tj << 7;   // output col block

    // ---- load 4 operand tiles (128 rows x 128 B each) with SW128 swizzle ----
    {
        const __nv_bfloat16* bases[4] = {
            g_xhi + (size_t)rowA * OUT_F, g_xlo + (size_t)rowA * OUT_F,
            g_xhi + (size_t)rowB * OUT_F, g_xlo + (size_t)rowB * OUT_F };
        const int offs[4] = { SM_AHI, SM_ALO, SM_BHI, SM_BLO };
        #pragma unroll
        for (int t = 0; t < 4; t++) {
            const uint4* sp = (const uint4*)bases[t];
            #pragma unroll
            for (int j = 0; j < 4; j++) {
                int idx = tid + j * 256;
                uint4 v = sp[idx];
                uint32_t bo = (uint32_t)(idx << 4);
                uint32_t sw = bo ^ ((bo >> 3) & 0x70);
                *(uint4*)(smem + offs[t] + sw) = v;
            }
        }
    }
    __syncthreads();

    float acc[2][8][4];
    #pragma unroll
    for (int mt = 0; mt < 2; mt++)
        #pragma unroll
        for (int nt = 0; nt < 8; nt++)
            #pragma unroll
            for (int e = 0; e < 4; e++) acc[mt][nt][e] = 0.f;

    int lrow = lid & 15;
    int lchk = lid >> 4;
    int lswz = lid & 7;

    #pragma unroll
    for (int kc = 0; kc < 4; kc++) {
        uint32_t chunk = (uint32_t)(((2 * kc + lchk) ^ lswz) << 4);
        uint32_t ah[2][4], al[2][4], bh[4][4], bl[4][4];
        #pragma unroll
        for (int mt = 0; mt < 2; mt++) {
            uint32_t ro = (uint32_t)((wm * 32 + mt * 16 + lrow) * 128) + chunk;
            ldsm_x4(ah[mt], sb + SM_AHI + ro);
            ldsm_x4(al[mt], sb + SM_ALO + ro);
        }
        #pragma unroll
        for (int np = 0; np < 4; np++) {
            uint32_t ro = (uint32_t)((wn * 64 + np * 16 + lrow) * 128) + chunk;
            ldsm_x4(bh[np], sb + SM_BHI + ro);
            ldsm_x4(bl[np], sb + SM_BLO + ro);
        }
        #pragma unroll
        for (int mt = 0; mt < 2; mt++)
            #pragma unroll
            for (int nt = 0; nt < 8; nt++) {
                int np = nt >> 1, sel = nt & 1;
                mma16816(acc[mt][nt], ah[mt], bh[np][sel], bh[np][sel + 2]); // hi*hi
                mma16816(acc[mt][nt], ah[mt], bl[np][sel], bl[np][sel + 2]); // hi*lo
                mma16816(acc[mt][nt], al[mt], bh[np][sel], bh[np][sel + 2]); // lo*hi
            }
    }
    __syncthreads();   // operands dead; reuse smem as fp32 stage

    float* stage = (float*)smem;    // [128][STAGE_STRIDE]
    int gid = lid >> 2, tig = lid & 3;

    // ---- pass 1: direct tile ----
    #pragma unroll
    for (int mt = 0; mt < 2; mt++)
        #pragma unroll
        for (int half = 0; half < 2; half++) {
            int r = wm * 32 + mt * 16 + gid + 8 * half;
            #pragma unroll
            for (int nt = 0; nt < 8; nt++) {
                int c = wn * 64 + nt * 8 + tig * 2;
                *(float2*)&stage[r * STAGE_STRIDE + c] =
                    make_float2(acc[mt][nt][half * 2], acc[mt][nt][half * 2 + 1]);
            }
        }
    __syncthreads();
    {
        size_t obase = (size_t)rowA * 16384 + rowB;
        #pragma unroll
        for (int it = 0; it < 16; it++) {
            int r = it * 8 + wid;
            float4 v = *(float4*)&stage[r * STAGE_STRIDE + lid * 4];
            *(float4*)(out + obase + (size_t)r * 16384 + lid * 4) = v;
        }
    }

    // ---- pass 2: transposed tile (skip on diagonal) ----
    if (ti != tj) {
        __syncthreads();
        #pragma unroll
        for (int mt = 0; mt < 2; mt++)
            #pragma unroll
            for (int half = 0; half < 2; half++) {
                int r = wm * 32 + mt * 16 + gid + 8 * half;
                #pragma unroll
                for (int nt = 0; nt < 8; nt++) {
                    int c = wn * 64 + nt * 8 + tig * 2;
                    stage[c * STAGE_STRIDE + r]       = acc[mt][nt][half * 2];
                    stage[(c + 1) * STAGE_STRIDE + r] = acc[mt][nt][half * 2 + 1];
                }
            }
        __syncthreads();
        size_t obase = (size_t)rowB * 16384 + rowA;
        #pragma unroll
        for (int it = 0; it < 16; it++) {
            int r = it * 8 + wid;
            float4 v = *(float4*)&stage[r * STAGE_STRIDE + lid * 4];
            *(float4*)(out + obase + (size_t)r * 16384 + lid * 4) = v;
        }
    }
}

// ---------------- launch ----------------
extern "C" void kernel_launch(void* const* d_in, const int* in_sizes, int n_in,
                              void* d_out, int out_size) {
    const float*        h    = (const float*)d_in[0];
    const unsigned int* srcw = (const unsigned int*)d_in[1];
    const unsigned int* dstw = (const unsigned int*)d_in[2];
    const float*        W    = (const float*)d_in[3];
    const float*        bias = (const float*)d_in[4];
    float*              out  = (float*)d_out;

    detect_kernel<<<1, 256>>>(srcw);
    kz_zero<<<N_NODES / 256, 256>>>();
    k1_proj<<<N_NODES / 8, 256>>>(h, W);
    k2a_hist<<<NE / 256, 256>>>(dstw);
    k2b_scan<<<1, 1024>>>();
    k2c_fill<<<NE / 256, 256>>>(srcw, dstw);
    k2d_gather<<<N_NODES / 8, 256>>>(bias);

    cudaFuncSetAttribute(k4_gemm, cudaFuncAttributeMaxDynamicSharedMemorySize, SM_TOTAL);
    k4_gemm<<<(128 * 129) / 2, 256, SM_TOTAL>>>(out);
}

// round 5
// speedup vs baseline: 1.3779x; 1.3259x over previous
#include <cuda_runtime.h>
#include <cuda_bf16.h>
#include <stdint.h>

// ---------------- problem constants ----------------
#define N_NODES 16384
#define NE      524288
#define IN_F    128
#define OUT_F   64

// ---------------- device scratch ----------------
__device__ float         g_hw [N_NODES * OUT_F];   // 4 MB
__device__ float         g_agg[N_NODES * OUT_F];   // 4 MB
__device__ __nv_bfloat16 g_xhi[N_NODES * OUT_F];   // 2 MB
__device__ __nv_bfloat16 g_xlo[N_NODES * OUT_F];   // 2 MB
__device__ int           g_is64;

// ---------------- launch 1: fused k1_proj + zero(agg) + int-width detect ----------------
// blocks [0,2048): projection rows; [2048,6144): zero g_agg; block 6144: detect.
__global__ __launch_bounds__(256) void k_fused1(const float* __restrict__ h,
                                                const float* __restrict__ W,
                                                const unsigned int* __restrict__ srcw) {
    int bid = blockIdx.x;
    int tid = threadIdx.x;
    if (bid < 2048) {
        __shared__ float sW[IN_F * OUT_F];  // 32 KB
        __shared__ float sH[8][IN_F];       // 4 KB
        int wid = tid >> 5, lid = tid & 31;
        for (int i = tid; i < IN_F * OUT_F; i += 256) sW[i] = W[i];
        int r = bid * 8 + wid;
        #pragma unroll
        for (int t = 0; t < 4; t++) sH[wid][lid + 32 * t] = h[(size_t)r * IN_F + lid + 32 * t];
        __syncthreads();
        float a0 = 0.f, a1 = 0.f;
        #pragma unroll
        for (int k = 0; k < IN_F; k++) {
            float hv = sH[wid][k];
            a0 += hv * sW[k * OUT_F + lid];
            a1 += hv * sW[k * OUT_F + lid + 32];
        }
        g_hw[r * OUT_F + lid]      = a0;
        g_hw[r * OUT_F + lid + 32] = a1;
    } else if (bid < 6144) {
        int i = (bid - 2048) * 256 + tid;
        g_agg[i] = 0.f;
    } else {
        __shared__ int cnt;
        if (tid == 0) cnt = 0;
        __syncthreads();
        int z = 0;
        for (int i = tid; i < 1024; i += 256)
            z += (srcw[2 * i + 1] == 0u) ? 1 : 0;
        atomicAdd(&cnt, z);
        __syncthreads();
        if (tid == 0) g_is64 = (cnt > 512) ? 1 : 0;
    }
}

// ---------------- launch 2: edge scatter via vector reductions ----------------
// Half-warp per edge: 16 lanes x red.global.add.v4.f32 (64 floats per edge).
__global__ __launch_bounds__(256) void k2_scatter(const unsigned int* __restrict__ srcw,
                                                  const unsigned int* __restrict__ dstw) {
    unsigned hw = (blockIdx.x * 256u + threadIdx.x) >> 4;   // half-warp id = edge id
    int sub = threadIdx.x & 15;                             // v4 slot within edge
    if (hw >= NE) return;
    int mul = g_is64 ? 2 : 1;
    unsigned s = srcw[(size_t)hw * mul];
    unsigned d = dstw[(size_t)hw * mul];
    const float4* src = (const float4*)g_hw;
    float4 v = src[s * 16 + sub];
    float* dst = &g_agg[d * OUT_F + sub * 4];
    asm volatile("red.global.add.v4.f32 [%0], {%1,%2,%3,%4};"
                 :: "l"(dst), "f"(v.x), "f"(v.y), "f"(v.z), "f"(v.w) : "memory");
}

// ---------------- threefry2x32 (JAX-exact, 20 rounds) ----------------
__device__ __forceinline__ void threefry2x32(uint32_t k0, uint32_t k1,
                                             uint32_t x0, uint32_t x1,
                                             uint32_t& o0, uint32_t& o1) {
    uint32_t ks0 = k0, ks1 = k1, ks2 = 0x1BD11BDAu ^ k0 ^ k1;
    x0 += ks0; x1 += ks1;
#define TF_R(rr) { x0 += x1; x1 = (x1 << (rr)) | (x1 >> (32 - (rr))); x1 ^= x0; }
    TF_R(13) TF_R(15) TF_R(26) TF_R(6)  x0 += ks1; x1 += ks2 + 1u;
    TF_R(17) TF_R(29) TF_R(16) TF_R(24) x0 += ks2; x1 += ks0 + 2u;
    TF_R(13) TF_R(15) TF_R(26) TF_R(6)  x0 += ks0; x1 += ks1 + 3u;
    TF_R(17) TF_R(29) TF_R(16) TF_R(24) x0 += ks1; x1 += ks2 + 4u;
    TF_R(13) TF_R(15) TF_R(26) TF_R(6)  x0 += ks2; x1 += ks0 + 5u;
#undef TF_R
    o0 = x0; o1 = x1;
}

// ---------------- launch 3: relu + dropout mask + bf16 hi/lo split ----------------
__global__ __launch_bounds__(256) void k3_mask(const float* __restrict__ bias) {
    int i = blockIdx.x * 256 + threadIdx.x;  // i < N*OUT_F
    uint32_t o0, o1;
    threefry2x32(0u, 42u, 0u, (uint32_t)i, o0, o1);
    uint32_t bits = o0 ^ o1;
    float u = __uint_as_float((bits >> 9) | 0x3f800000u) - 1.0f;
    float v = g_agg[i] + bias[i & 63];
    v = fmaxf(v, 0.0f);
    float y = (u < 0.7f) ? (v / 0.7f) : 0.0f;
    __nv_bfloat16 hi = __float2bfloat16(y);
    g_xhi[i] = hi;
    g_xlo[i] = __float2bfloat16(y - __bfloat162float(hi));
}

// ---------------- launch 4: out = x @ x^T, symmetric (triangular grid) ----------------
#define SM_AHI  0
#define SM_ALO  16384
#define SM_BHI  32768
#define SM_BLO  49152
#define STAGE_STRIDE 136
#define SM_TOTAL (128 * STAGE_STRIDE * 4)   // 69632 B

__device__ __forceinline__ void ldsm_x4(uint32_t* r, uint32_t addr) {
    asm volatile("ldmatrix.sync.aligned.m8n8.x4.shared.b16 {%0,%1,%2,%3}, [%4];"
                 : "=r"(r[0]), "=r"(r[1]), "=r"(r[2]), "=r"(r[3]) : "r"(addr));
}
__device__ __forceinline__ void mma16816(float* d, const uint32_t* a,
                                         uint32_t b0, uint32_t b1) {
    asm volatile(
        "mma.sync.aligned.m16n8k16.row.col.f32.bf16.bf16.f32 "
        "{%0,%1,%2,%3}, {%4,%5,%6,%7}, {%8,%9}, {%0,%1,%2,%3};"
        : "+f"(d[0]), "+f"(d[1]), "+f"(d[2]), "+f"(d[3])
        : "r"(a[0]), "r"(a[1]), "r"(a[2]), "r"(a[3]), "r"(b0), "r"(b1));
}
__device__ __forceinline__ void stg_cs(float* p, float4 v) {
    asm volatile("st.global.cs.v4.f32 [%0], {%1,%2,%3,%4};"
                 :: "l"(p), "f"(v.x), "f"(v.y), "f"(v.z), "f"(v.w) : "memory");
}

__global__ __launch_bounds__(256, 2)
void k4_gemm(float* __restrict__ out) {
    extern __shared__ char smem[];
    uint32_t sb = (uint32_t)__cvta_generic_to_shared(smem);
    int tid = threadIdx.x, wid = tid >> 5, lid = tid & 31;
    int wm = wid & 3, wn = wid >> 2;

    // triangular decode: bid -> (ti <= tj)
    int bid = blockIdx.x;
    int ti = (int)((257.0 - sqrt(66049.0 - 8.0 * (double)bid)) * 0.5);
    while ((ti + 1) * 128 - ((ti + 1) * ti) / 2 <= bid) ti++;
    while (ti * 128 - (ti * (ti - 1)) / 2 > bid) ti--;
    int tj = ti + (bid - (ti * 128 - (ti * (ti - 1)) / 2));
    int rowA = ti << 7;
    int rowB = tj << 7;

    // ---- load 4 operand tiles (128 rows x 128 B each) with SW128 swizzle ----
    {
        const __nv_bfloat16* bases[4] = {
            g_xhi + (size_t)rowA * OUT_F, g_xlo + (size_t)rowA * OUT_F,
            g_xhi + (size_t)rowB * OUT_F, g_xlo + (size_t)rowB * OUT_F };
        const int offs[4] = { SM_AHI, SM_ALO, SM_BHI, SM_BLO };
        #pragma unroll
        for (int t = 0; t < 4; t++) {
            const uint4* sp = (const uint4*)bases[t];
            #pragma unroll
            for (int j = 0; j < 4; j++) {
                int idx = tid + j * 256;
                uint4 v = sp[idx];
                uint32_t bo = (uint32_t)(idx << 4);
                uint32_t sw = bo ^ ((bo >> 3) & 0x70);
                *(uint4*)(smem + offs[t] + sw) = v;
            }
        }
    }
    __syncthreads();

    float acc[2][8][4];
    #pragma unroll
    for (int mt = 0; mt < 2; mt++)
        #pragma unroll
        for (int nt = 0; nt < 8; nt++)
            #pragma unroll
            for (int e = 0; e < 4; e++) acc[mt][nt][e] = 0.f;

    int lrow = lid & 15;
    int lchk = lid >> 4;
    int lswz = lid & 7;

    #pragma unroll
    for (int kc = 0; kc < 4; kc++) {
        uint32_t chunk = (uint32_t)(((2 * kc + lchk) ^ lswz) << 4);
        uint32_t ah[2][4], al[2][4], bh[4][4], bl[4][4];
        #pragma unroll
        for (int mt = 0; mt < 2; mt++) {
            uint32_t ro = (uint32_t)((wm * 32 + mt * 16 + lrow) * 128) + chunk;
            ldsm_x4(ah[mt], sb + SM_AHI + ro);
            ldsm_x4(al[mt], sb + SM_ALO + ro);
        }
        #pragma unroll
        for (int np = 0; np < 4; np++) {
            uint32_t ro = (uint32_t)((wn * 64 + np * 16 + lrow) * 128) + chunk;
            ldsm_x4(bh[np], sb + SM_BHI + ro);
            ldsm_x4(bl[np], sb + SM_BLO + ro);
        }
        #pragma unroll
        for (int mt = 0; mt < 2; mt++)
            #pragma unroll
            for (int nt = 0; nt < 8; nt++) {
                int np = nt >> 1, sel = nt & 1;
                mma16816(acc[mt][nt], ah[mt], bh[np][sel], bh[np][sel + 2]); // hi*hi
                mma16816(acc[mt][nt], ah[mt], bl[np][sel], bl[np][sel + 2]); // hi*lo
                mma16816(acc[mt][nt], al[mt], bh[np][sel], bh[np][sel + 2]); // lo*hi
            }
    }
    __syncthreads();   // operands dead; reuse smem as fp32 stage

    float* stage = (float*)smem;    // [128][STAGE_STRIDE]
    int gid = lid >> 2, tig = lid & 3;

    // ---- pass 1: direct tile ----
    #pragma unroll
    for (int mt = 0; mt < 2; mt++)
        #pragma unroll
        for (int half = 0; half < 2; half++) {
            int r = wm * 32 + mt * 16 + gid + 8 * half;
            #pragma unroll
            for (int nt = 0; nt < 8; nt++) {
                int c = wn * 64 + nt * 8 + tig * 2;
                *(float2*)&stage[r * STAGE_STRIDE + c] =
                    make_float2(acc[mt][nt][half * 2], acc[mt][nt][half * 2 + 1]);
            }
        }
    __syncthreads();
    {
        size_t obase = (size_t)rowA * 16384 + rowB;
        #pragma unroll
        for (int it = 0; it < 16; it++) {
            int r = it * 8 + wid;
            float4 v = *(float4*)&stage[r * STAGE_STRIDE + lid * 4];
            stg_cs(out + obase + (size_t)r * 16384 + lid * 4, v);
        }
    }

    // ---- pass 2: transposed tile (skip on diagonal) ----
    if (ti != tj) {
        __syncthreads();
        #pragma unroll
        for (int mt = 0; mt < 2; mt++)
            #pragma unroll
            for (int half = 0; half < 2; half++) {
                int r = wm * 32 + mt * 16 + gid + 8 * half;
                #pragma unroll
                for (int nt = 0; nt < 8; nt++) {
                    int c = wn * 64 + nt * 8 + tig * 2;
                    stage[c * STAGE_STRIDE + r]       = acc[mt][nt][half * 2];
                    stage[(c + 1) * STAGE_STRIDE + r] = acc[mt][nt][half * 2 + 1];
                }
            }
        __syncthreads();
        size_t obase = (size_t)rowB * 16384 + rowA;
        #pragma unroll
        for (int it = 0; it < 16; it++) {
            int r = it * 8 + wid;
            float4 v = *(float4*)&stage[r * STAGE_STRIDE + lid * 4];
            stg_cs(out + obase + (size_t)r * 16384 + lid * 4, v);
        }
    }
}

// ---------------- launch ----------------
extern "C" void kernel_launch(void* const* d_in, const int* in_sizes, int n_in,
                              void* d_out, int out_size) {
    const float*        h    = (const float*)d_in[0];
    const unsigned int* srcw = (const unsigned int*)d_in[1];
    const unsigned int* dstw = (const unsigned int*)d_in[2];
    const float*        W    = (const float*)d_in[3];
    const float*        bias = (const float*)d_in[4];
    float*              out  = (float*)d_out;

    k_fused1<<<6145, 256>>>(h, W, srcw);                 // launch 1
    k2_scatter<<<(NE * 16) / 256, 256>>>(srcw, dstw);    // launch 2
    k3_mask<<<(N_NODES * OUT_F) / 256, 256>>>(bias);     // launch 3

    cudaFuncSetAttribute(k4_gemm, cudaFuncAttributeMaxDynamicSharedMemorySize, SM_TOTAL);
    k4_gemm<<<(128 * 129) / 2, 256, SM_TOTAL>>>(out);    // launch 4 (ncu target)
}

// round 7
// speedup vs baseline: 1.3801x; 1.0016x over previous
#include <cuda_runtime.h>
#include <cuda_bf16.h>
#include <stdint.h>

// ---------------- problem constants ----------------
#define N_NODES 16384
#define NE      524288
#define IN_F    128
#define OUT_F   64

// ---------------- device scratch ----------------
__device__ float         g_hw [N_NODES * OUT_F];   // 4 MB
__device__ float         g_agg[N_NODES * OUT_F];   // 4 MB
__device__ __nv_bfloat16 g_xhi[N_NODES * OUT_F];   // 2 MB
__device__ __nv_bfloat16 g_xlo[N_NODES * OUT_F];   // 2 MB
__device__ int           g_is64;

// ---------------- launch 1: fused k1_proj + zero(agg) + int-width detect ----------------
__global__ __launch_bounds__(256) void k_fused1(const float* __restrict__ h,
                                                const float* __restrict__ W,
                                                const unsigned int* __restrict__ srcw) {
    int bid = blockIdx.x;
    int tid = threadIdx.x;
    if (bid < 2048) {
        __shared__ float sW[IN_F * OUT_F];  // 32 KB
        __shared__ float sH[8][IN_F];       // 4 KB
        int wid = tid >> 5, lid = tid & 31;
        for (int i = tid; i < IN_F * OUT_F; i += 256) sW[i] = W[i];
        int r = bid * 8 + wid;
        #pragma unroll
        for (int t = 0; t < 4; t++) sH[wid][lid + 32 * t] = h[(size_t)r * IN_F + lid + 32 * t];
        __syncthreads();
        float a0 = 0.f, a1 = 0.f;
        #pragma unroll
        for (int k = 0; k < IN_F; k++) {
            float hv = sH[wid][k];
            a0 += hv * sW[k * OUT_F + lid];
            a1 += hv * sW[k * OUT_F + lid + 32];
        }
        g_hw[r * OUT_F + lid]      = a0;
        g_hw[r * OUT_F + lid + 32] = a1;
    } else if (bid < 6144) {
        int i = (bid - 2048) * 256 + tid;
        g_agg[i] = 0.f;
    } else {
        __shared__ int cnt;
        if (tid == 0) cnt = 0;
        __syncthreads();
        int z = 0;
        for (int i = tid; i < 1024; i += 256)
            z += (srcw[2 * i + 1] == 0u) ? 1 : 0;
        atomicAdd(&cnt, z);
        __syncthreads();
        if (tid == 0) g_is64 = (cnt > 512) ? 1 : 0;
    }
}

// ---------------- launch 2: edge scatter via vector reductions ----------------
__global__ __launch_bounds__(256) void k2_scatter(const unsigned int* __restrict__ srcw,
                                                  const unsigned int* __restrict__ dstw) {
    unsigned hw = (blockIdx.x * 256u + threadIdx.x) >> 4;   // half-warp id = edge id
    int sub = threadIdx.x & 15;
    if (hw >= NE) return;
    int mul = g_is64 ? 2 : 1;
    unsigned s = srcw[(size_t)hw * mul];
    unsigned d = dstw[(size_t)hw * mul];
    const float4* src = (const float4*)g_hw;
    float4 v = src[s * 16 + sub];
    float* dst = &g_agg[d * OUT_F + sub * 4];
    asm volatile("red.global.add.v4.f32 [%0], {%1,%2,%3,%4};"
                 :: "l"(dst), "f"(v.x), "f"(v.y), "f"(v.z), "f"(v.w) : "memory");
}

// ---------------- threefry2x32 (JAX-exact, 20 rounds) ----------------
__device__ __forceinline__ void threefry2x32(uint32_t k0, uint32_t k1,
                                             uint32_t x0, uint32_t x1,
                                             uint32_t& o0, uint32_t& o1) {
    uint32_t ks0 = k0, ks1 = k1, ks2 = 0x1BD11BDAu ^ k0 ^ k1;
    x0 += ks0; x1 += ks1;
#define TF_R(rr) { x0 += x1; x1 = (x1 << (rr)) | (x1 >> (32 - (rr))); x1 ^= x0; }
    TF_R(13) TF_R(15) TF_R(26) TF_R(6)  x0 += ks1; x1 += ks2 + 1u;
    TF_R(17) TF_R(29) TF_R(16) TF_R(24) x0 += ks2; x1 += ks0 + 2u;
    TF_R(13) TF_R(15) TF_R(26) TF_R(6)  x0 += ks0; x1 += ks1 + 3u;
    TF_R(17) TF_R(29) TF_R(16) TF_R(24) x0 += ks1; x1 += ks2 + 4u;
    TF_R(13) TF_R(15) TF_R(26) TF_R(6)  x0 += ks2; x1 += ks0 + 5u;
#undef TF_R
    o0 = x0; o1 = x1;
}

// ---------------- launch 3: relu + dropout mask + bf16 hi/lo split ----------------
__global__ __launch_bounds__(256) void k3_mask(const float* __restrict__ bias) {
    int i = blockIdx.x * 256 + threadIdx.x;
    uint32_t o0, o1;
    threefry2x32(0u, 42u, 0u, (uint32_t)i, o0, o1);
    uint32_t bits = o0 ^ o1;
    float u = __uint_as_float((bits >> 9) | 0x3f800000u) - 1.0f;
    float v = g_agg[i] + bias[i & 63];
    v = fmaxf(v, 0.0f);
    float y = (u < 0.7f) ? (v / 0.7f) : 0.0f;
    __nv_bfloat16 hi = __float2bfloat16(y);
    g_xhi[i] = hi;
    g_xlo[i] = __float2bfloat16(y - __bfloat162float(hi));
}

// ---------------- launch 4: out = x @ x^T, symmetric, 512 threads / 4x4 warp grid ----
#define SM_AHI  0
#define SM_ALO  16384
#define SM_BHI  32768
#define SM_BLO  49152
#define STAGE_STRIDE 136
#define SM_TOTAL (128 * STAGE_STRIDE * 4)   // 69632 B

__device__ __forceinline__ void ldsm_x4(uint32_t* r, uint32_t addr) {
    asm volatile("ldmatrix.sync.aligned.m8n8.x4.shared.b16 {%0,%1,%2,%3}, [%4];"
                 : "=r"(r[0]), "=r"(r[1]), "=r"(r[2]), "=r"(r[3]) : "r"(addr));
}
__device__ __forceinline__ void mma16816(float* d, const uint32_t* a,
                                         uint32_t b0, uint32_t b1) {
    asm volatile(
        "mma.sync.aligned.m16n8k16.row.col.f32.bf16.bf16.f32 "
        "{%0,%1,%2,%3}, {%4,%5,%6,%7}, {%8,%9}, {%0,%1,%2,%3};"
        : "+f"(d[0]), "+f"(d[1]), "+f"(d[2]), "+f"(d[3])
        : "r"(a[0]), "r"(a[1]), "r"(a[2]), "r"(a[3]), "r"(b0), "r"(b1));
}
__device__ __forceinline__ void stg_cs(float* p, float4 v) {
    asm volatile("st.global.cs.v4.f32 [%0], {%1,%2,%3,%4};"
                 :: "l"(p), "f"(v.x), "f"(v.y), "f"(v.z), "f"(v.w) : "memory");
}
__device__ __forceinline__ void cp_async16(uint32_t saddr, const void* gptr) {
    asm volatile("cp.async.cg.shared.global [%0], [%1], 16;"
                 :: "r"(saddr), "l"(gptr) : "memory");
}

__global__ __launch_bounds__(512, 2)
void k4_gemm(float* __restrict__ out) {
    extern __shared__ char smem[];
    uint32_t sb = (uint32_t)__cvta_generic_to_shared(smem);
    int tid = threadIdx.x, wid = tid >> 5, lid = tid & 31;
    int wm = wid & 3, wn = wid >> 2;   // 4x4 warp grid, warp tile 32 rows x 32 cols

    // triangular decode: bid -> (ti <= tj)
    int bid = blockIdx.x;
    int ti = (int)((257.0 - sqrt(66049.0 - 8.0 * (double)bid)) * 0.5);
    while ((ti + 1) * 128 - ((ti + 1) * ti) / 2 <= bid) ti++;
    while (ti * 128 - (ti * (ti - 1)) / 2 > bid) ti--;
    int tj = ti + (bid - (ti * 128 - (ti * (ti - 1)) / 2));
    int rowA = ti << 7;
    int rowB = tj << 7;

    // ---- prologue: cp.async the 4 operand tiles (128 rows x 128 B) with SW128 swizzle ----
    {
        const __nv_bfloat16* bases[4] = {
            g_xhi + (size_t)rowA * OUT_F, g_xlo + (size_t)rowA * OUT_F,
            g_xhi + (size_t)rowB * OUT_F, g_xlo + (size_t)rowB * OUT_F };
        const int offs[4] = { SM_AHI, SM_ALO, SM_BHI, SM_BLO };
        #pragma unroll
        for (int t = 0; t < 4; t++) {
            const char* gp = (const char*)bases[t];
            #pragma unroll
            for (int j = 0; j < 2; j++) {
                int idx = tid + j * 512;                 // 1024 x 16B chunks
                uint32_t bo = (uint32_t)(idx << 4);
                uint32_t sw = bo ^ ((bo >> 3) & 0x70);
                cp_async16(sb + offs[t] + sw, gp + ((size_t)idx << 4));
            }
        }
        asm volatile("cp.async.commit_group;" ::: "memory");
        asm volatile("cp.async.wait_group 0;" ::: "memory");
    }
    __syncthreads();

    float acc[2][4][4];
    #pragma unroll
    for (int mt = 0; mt < 2; mt++)
        #pragma unroll
        for (int nt = 0; nt < 4; nt++)
            #pragma unroll
            for (int e = 0; e < 4; e++) acc[mt][nt][e] = 0.f;

    int lrow = lid & 15;
    int lchk = lid >> 4;
    int lswz = lid & 7;

    #pragma unroll
    for (int kc = 0; kc < 4; kc++) {
        uint32_t chunk = (uint32_t)(((2 * kc + lchk) ^ lswz) << 4);
        uint32_t ah[2][4], al[2][4];
        #pragma unroll
        for (int mt = 0; mt < 2; mt++) {
            uint32_t ro = (uint32_t)((wm * 32 + mt * 16 + lrow) * 128) + chunk;
            ldsm_x4(ah[mt], sb + SM_AHI + ro);
            ldsm_x4(al[mt], sb + SM_ALO + ro);
        }
        #pragma unroll
        for (int np = 0; np < 2; np++) {        // B 16-col group at a time (reg pressure)
            uint32_t bh[4], bl[4];
            uint32_t ro = (uint32_t)((wn * 32 + np * 16 + lrow) * 128) + chunk;
            ldsm_x4(bh, sb + SM_BHI + ro);
            ldsm_x4(bl, sb + SM_BLO + ro);
            #pragma unroll
            for (int mt = 0; mt < 2; mt++)
                #pragma unroll
                for (int sel = 0; sel < 2; sel++) {
                    int nt = np * 2 + sel;
                    mma16816(acc[mt][nt], ah[mt], bh[sel], bh[sel + 2]); // hi*hi
                    mma16816(acc[mt][nt], ah[mt], bl[sel], bl[sel + 2]); // hi*lo
                    mma16816(acc[mt][nt], al[mt], bh[sel], bh[sel + 2]); // lo*hi
                }
        }
    }
    __syncthreads();   // operands dead; reuse smem as fp32 stage

    float* stage = (float*)smem;    // [128][STAGE_STRIDE]
    int gid = lid >> 2, tig = lid & 3;

    // ---- pass 1: direct tile ----
    #pragma unroll
    for (int mt = 0; mt < 2; mt++)
        #pragma unroll
        for (int half = 0; half < 2; half++) {
            int r = wm * 32 + mt * 16 + gid + 8 * half;
            #pragma unroll
            for (int nt = 0; nt < 4; nt++) {
                int c = wn * 32 + nt * 8 + tig * 2;
                *(float2*)&stage[r * STAGE_STRIDE + c] =
                    make_float2(acc[mt][nt][half * 2], acc[mt][nt][half * 2 + 1]);
            }
        }
    __syncthreads();
    {
        size_t obase = (size_t)rowA * 16384 + rowB;
        #pragma unroll
        for (int it = 0; it < 8; it++) {
            int r = it * 16 + wid;
            float4 v = *(float4*)&stage[r * STAGE_STRIDE + lid * 4];
            stg_cs(out + obase + (size_t)r * 16384 + lid * 4, v);
        }
    }

    // ---- pass 2: transposed tile (skip on diagonal) ----
    if (ti != tj) {
        __syncthreads();
        #pragma unroll
        for (int mt = 0; mt < 2; mt++)
            #pragma unroll
            for (int half = 0; half < 2; half++) {
                int r = wm * 32 + mt * 16 + gid + 8 * half;
                #pragma unroll
                for (int nt = 0; nt < 4; nt++) {
                    int c = wn * 32 + nt * 8 + tig * 2;
                    stage[c * STAGE_STRIDE + r]       = acc[mt][nt][half * 2];
                    stage[(c + 1) * STAGE_STRIDE + r] = acc[mt][nt][half * 2 + 1];
                }
            }
        __syncthreads();
        size_t obase = (size_t)rowB * 16384 + rowA;
        #pragma unroll
        for (int it = 0; it < 8; it++) {
            int r = it * 16 + wid;
            float4 v = *(float4*)&stage[r * STAGE_STRIDE + lid * 4];
            stg_cs(out + obase + (size_t)r * 16384 + lid * 4, v);
        }
    }
}

// ---------------- launch ----------------
extern "C" void kernel_launch(void* const* d_in, const int* in_sizes, int n_in,
                              void* d_out, int out_size) {
    const float*        h    = (const float*)d_in[0];
    const unsigned int* srcw = (const unsigned int*)d_in[1];
    const unsigned int* dstw = (const unsigned int*)d_in[2];
    const float*        W    = (const float*)d_in[3];
    const float*        bias = (const float*)d_in[4];
    float*              out  = (float*)d_out;

    k_fused1<<<6145, 256>>>(h, W, srcw);                 // launch 1
    k2_scatter<<<(NE * 16) / 256, 256>>>(srcw, dstw);    // launch 2
    k3_mask<<<(N_NODES * OUT_F) / 256, 256>>>(bias);     // launch 3

    cudaFuncSetAttribute(k4_gemm, cudaFuncAttributeMaxDynamicSharedMemorySize, SM_TOTAL);
    k4_gemm<<<(128 * 129) / 2, 512, SM_TOTAL>>>(out);    // launch 4 (ncu target)
}